// round 3
// baseline (speedup 1.0000x reference)
#include <cuda_runtime.h>
#include <cuda_bf16.h>
#include <cstdint>
#include <cstddef>

// Problem constants
#define L_SEQ  2048
#define BATCH  32
#define DIM    512
#define NLAY   4
#define MTOT   (L_SEQ*BATCH)   // 65536
#define NTOT   (3*DIM)         // 1536

// ---------------- device-global scratch (sanctioned no-alloc path) ---------
__device__ __nv_bfloat16 g_h_hi[(size_t)MTOT*DIM];       // 64 MB
__device__ __nv_bfloat16 g_h_lo[(size_t)MTOT*DIM];       // 64 MB
__device__ __nv_bfloat16 g_W_hi[(size_t)NLAY*NTOT*DIM];  // 6 MB  [l][n][k]
__device__ __nv_bfloat16 g_W_lo[(size_t)NLAY*NTOT*DIM];  // 6 MB
__device__ float         g_U[(size_t)MTOT*NTOT];         // 384 MB [m][n]

// ---------------- helpers ---------------------------------------------------
__device__ __forceinline__ uint32_t smem_u32(const void* p) {
    uint32_t a;
    asm("{ .reg .u64 t; cvta.to.shared.u64 t, %1; cvt.u32.u64 %0, t; }"
        : "=r"(a) : "l"(p));
    return a;
}
__device__ __forceinline__ void cp16(uint32_t dst, const void* src) {
    asm volatile("cp.async.cg.shared.global [%0], [%1], 16;\n"
                 :: "r"(dst), "l"(src));
}
#define CP_COMMIT() asm volatile("cp.async.commit_group;")

__device__ __forceinline__ void ldsm4(uint32_t* r, uint32_t addr) {
    asm volatile("ldmatrix.sync.aligned.m8n8.x4.shared.b16 {%0,%1,%2,%3}, [%4];"
                 : "=r"(r[0]), "=r"(r[1]), "=r"(r[2]), "=r"(r[3]) : "r"(addr));
}
__device__ __forceinline__ void mma16816(float* d, const uint32_t* a, const uint32_t* b) {
    asm volatile("mma.sync.aligned.m16n8k16.row.col.f32.bf16.bf16.f32 "
                 "{%0,%1,%2,%3}, {%4,%5,%6,%7}, {%8,%9}, {%0,%1,%2,%3};"
                 : "+f"(d[0]), "+f"(d[1]), "+f"(d[2]), "+f"(d[3])
                 : "r"(a[0]), "r"(a[1]), "r"(a[2]), "r"(a[3]),
                   "r"(b[0]), "r"(b[1]));
}

// ---------------- GEMM config ----------------------------------------------
// CTA tile 128x128, BK=64 (128B rows), 2-stage cp.async pipeline,
// bf16x3 compensated passes accumulated into the same fp32 accumulators.
#define MT 128
#define NT 128
#define KC 64
#define NCHUNK (DIM/KC)                   // 8
#define TILE_BYTES 16384                  // 128 rows x 128 B
#define OFF_AH 0
#define OFF_AL 16384
#define OFF_BH 32768
#define OFF_BL 49152
#define STAGE_BYTES 65536
#define SMEM_TOTAL (2*STAGE_BYTES)        // 131072

// swizzled byte offset inside a 128x128B tile
__device__ __forceinline__ uint32_t swz(uint32_t row, uint32_t chunk) {
    return row * 128u + (((chunk ^ (row & 7u)) & 7u) << 4);
}

// load one 128x64 bf16 tile (cp.async), swizzled
__device__ __forceinline__ void load_tile(uint32_t dst_base,
                                          const __nv_bfloat16* __restrict__ src,
                                          int kc, int tid)
{
    #pragma unroll
    for (int i = 0; i < 4; i++) {
        int o = tid + (i << 8);
        uint32_t r = (uint32_t)(o >> 3), c = (uint32_t)(o & 7);
        cp16(dst_base + swz(r, c), src + (size_t)r * DIM + kc + (c << 3));
    }
}

__global__ void __launch_bounds__(256, 1)
gemm_kernel(int layer, int n_tiles)
{
    extern __shared__ __align__(1024) char smem[];
    uint32_t sb = smem_u32(smem);
    int tid  = threadIdx.x;
    int wid  = tid >> 5, lane = tid & 31;
    int wm   = wid & 3;         // 4 warps along M (32 rows each)
    int wn   = wid >> 2;        // 2 warps along N (64 cols each)
    int m0   = (blockIdx.x / n_tiles) * MT;
    int n0   = (blockIdx.x % n_tiles) * NT;

    const __nv_bfloat16* ah = g_h_hi + (size_t)m0 * DIM;
    const __nv_bfloat16* al = g_h_lo + (size_t)m0 * DIM;
    const __nv_bfloat16* bh = g_W_hi + ((size_t)layer * NTOT + n0) * DIM;
    const __nv_bfloat16* bl = g_W_lo + ((size_t)layer * NTOT + n0) * DIM;

    // ldmatrix per-lane geometry
    int t  = lane >> 3;              // which 8x8 within .x4
    int lr = lane & 7;               // row within 8x8
    uint32_t rA0 = (uint32_t)(wm * 32 + ((t & 1) << 3) + lr);
    uint32_t rB0 = (uint32_t)(wn * 64 + ((t & 1) << 3) + lr);
    uint32_t chi = (uint32_t)(t >> 1);

    float acc[2][8][4];
    #pragma unroll
    for (int i = 0; i < 2; i++)
        #pragma unroll
        for (int j = 0; j < 8; j++)
            #pragma unroll
            for (int q = 0; q < 4; q++) acc[i][j][q] = 0.f;

    // prologue: stages 0,1
    {
        uint32_t st0 = sb;
        load_tile(st0 + OFF_AH, ah, 0, tid);
        load_tile(st0 + OFF_AL, al, 0, tid);
        load_tile(st0 + OFF_BH, bh, 0, tid);
        load_tile(st0 + OFF_BL, bl, 0, tid);
        CP_COMMIT();
        uint32_t st1 = sb + STAGE_BYTES;
        load_tile(st1 + OFF_AH, ah, KC, tid);
        load_tile(st1 + OFF_AL, al, KC, tid);
        load_tile(st1 + OFF_BH, bh, KC, tid);
        load_tile(st1 + OFF_BL, bl, KC, tid);
        CP_COMMIT();
    }

    for (int chunk = 0; chunk < NCHUNK; ++chunk) {
        int s = chunk & 1;
        if (chunk < NCHUNK - 1) asm volatile("cp.async.wait_group 1;" ::: "memory");
        else                    asm volatile("cp.async.wait_group 0;" ::: "memory");
        __syncthreads();

        uint32_t st = sb + (uint32_t)s * STAGE_BYTES;
        #pragma unroll
        for (int ks = 0; ks < 4; ks++) {
            uint32_t cc = 2u * ks + chi;
            uint32_t aH[2][4], aL[2][4], bH[8][2], bL[8][2];
            #pragma unroll
            for (int mt = 0; mt < 2; mt++) {
                uint32_t rr = rA0 + (uint32_t)(mt << 4);
                uint32_t off = swz(rr, cc);
                ldsm4(aH[mt], st + OFF_AH + off);
                ldsm4(aL[mt], st + OFF_AL + off);
            }
            #pragma unroll
            for (int bt = 0; bt < 4; bt++) {
                uint32_t rr = rB0 + (uint32_t)(bt << 4);
                uint32_t off = swz(rr, cc);
                uint32_t r4[4];
                ldsm4(r4, st + OFF_BH + off);
                bH[2*bt][0] = r4[0]; bH[2*bt][1] = r4[2];
                bH[2*bt+1][0] = r4[1]; bH[2*bt+1][1] = r4[3];
                ldsm4(r4, st + OFF_BL + off);
                bL[2*bt][0] = r4[0]; bL[2*bt][1] = r4[2];
                bL[2*bt+1][0] = r4[1]; bL[2*bt+1][1] = r4[3];
            }
            #pragma unroll
            for (int mt = 0; mt < 2; mt++)
                #pragma unroll
                for (int nt = 0; nt < 8; nt++) {
                    mma16816(acc[mt][nt], aH[mt], bH[nt]);
                    mma16816(acc[mt][nt], aH[mt], bL[nt]);
                    mma16816(acc[mt][nt], aL[mt], bH[nt]);
                }
        }
        __syncthreads();

        if (chunk + 2 < NCHUNK) {
            int kc = (chunk + 2) * KC;
            load_tile(st + OFF_AH, ah, kc, tid);
            load_tile(st + OFF_AL, al, kc, tid);
            load_tile(st + OFF_BH, bh, kc, tid);
            load_tile(st + OFF_BL, bl, kc, tid);
        }
        CP_COMMIT();   // keep group count in lockstep even when empty
    }

    // epilogue: write U
    int rbase = lane >> 2;
    int cbase = (lane & 3) * 2;
    #pragma unroll
    for (int mt = 0; mt < 2; mt++) {
        int mrow = m0 + wm * 32 + mt * 16 + rbase;
        #pragma unroll
        for (int nt = 0; nt < 8; nt++) {
            int ncol = n0 + wn * 64 + nt * 8 + cbase;
            float2 v0 = make_float2(acc[mt][nt][0], acc[mt][nt][1]);
            float2 v1 = make_float2(acc[mt][nt][2], acc[mt][nt][3]);
            *(float2*)(g_U + (size_t)mrow * NTOT + ncol)       = v0;
            *(float2*)(g_U + (size_t)(mrow + 8) * NTOT + ncol) = v1;
        }
    }
}

// ---------------- pre-pass: split/transpose inputs --------------------------
// x[b][t][d] fp32 -> g_h_{hi,lo}[(t*B+b)][d] bf16x2 split
__global__ void __launch_bounds__(128)
split_x_kernel(const float* __restrict__ x)
{
    int e = blockIdx.x;                  // e = b*L + t
    int b = e >> 11, tt = e & (L_SEQ - 1);
    const float4* src = (const float4*)(x + (size_t)e * DIM);
    size_t drow = (size_t)(tt * BATCH + b) * DIM;
    int i = threadIdx.x;
    float4 v = src[i];
    __nv_bfloat16 h0 = __float2bfloat16(v.x), h1 = __float2bfloat16(v.y);
    __nv_bfloat16 h2 = __float2bfloat16(v.z), h3 = __float2bfloat16(v.w);
    __nv_bfloat16 l0 = __float2bfloat16(v.x - __bfloat162float(h0));
    __nv_bfloat16 l1 = __float2bfloat16(v.y - __bfloat162float(h1));
    __nv_bfloat16 l2 = __float2bfloat16(v.z - __bfloat162float(h2));
    __nv_bfloat16 l3 = __float2bfloat16(v.w - __bfloat162float(h3));
    union { __nv_bfloat16 h[4]; uint2 u; } ph, pl;
    ph.h[0] = h0; ph.h[1] = h1; ph.h[2] = h2; ph.h[3] = h3;
    pl.h[0] = l0; pl.h[1] = l1; pl.h[2] = l2; pl.h[3] = l3;
    *(uint2*)(g_h_hi + drow + 4 * i) = ph.u;
    *(uint2*)(g_h_lo + drow + 4 * i) = pl.u;
}

// W[l][k][n] fp32 -> g_W_{hi,lo}[l][n][k] bf16x2 split
__global__ void __launch_bounds__(256)
split_w_kernel(const float* __restrict__ W)
{
    int o = blockIdx.x * 256 + threadIdx.x;           // [l][n][k] linear
    int l = o / (NTOT * DIM);
    int rem = o - l * (NTOT * DIM);
    int n = rem >> 9, k = rem & (DIM - 1);
    float w = W[(size_t)l * DIM * NTOT + (size_t)k * NTOT + n];
    __nv_bfloat16 hi = __float2bfloat16(w);
    g_W_hi[o] = hi;
    g_W_lo[o] = __float2bfloat16(w - __bfloat162float(hi));
}

// ---------------- recurrence -------------------------------------------------
// one thread per (b,d) chain; depth-8 register prefetch
__global__ void __launch_bounds__(128)
recur_kernel(const float* __restrict__ state, const float* __restrict__ vc,
             const float* __restrict__ bias, const int* __restrict__ mask,
             float* __restrict__ out, int layer, int last)
{
    int g = blockIdx.x * 128 + threadIdx.x;           // 0..16383
    int b = g >> 9, d = g & (DIM - 1);
    float vf = vc[layer * 2 * DIM + d];
    float vr = vc[layer * 2 * DIM + DIM + d];
    float bf = bias[layer * 2 * DIM + d];
    float br = bias[layer * 2 * DIM + DIM + d];
    float c  = state[layer * DIM + d];

    const float* u = g_U + (size_t)b * NTOT + d;      // +t*BATCH*NTOT per step
    __nv_bfloat16* hh = g_h_hi + (size_t)b * DIM + d; // +t*BATCH*DIM per step
    __nv_bfloat16* hl = g_h_lo + (size_t)b * DIM + d;
    const int* mk = mask + b * L_SEQ;

    const int P = 8;
    const size_t SU = (size_t)BATCH * NTOT;           // 49152
    const size_t SH = (size_t)BATCH * DIM;            // 16384

    float u0b[P], u1b[P], u2b[P];
    __nv_bfloat16 xh[P], xl[P];
    int mkb[P];
    #pragma unroll
    for (int j = 0; j < P; j++) {
        const float* up = u + (size_t)j * SU;
        u0b[j] = up[0]; u1b[j] = up[DIM]; u2b[j] = up[2 * DIM];
        xh[j] = hh[(size_t)j * SH];
        xl[j] = hl[(size_t)j * SH];
        mkb[j] = mk[j];
    }

    #pragma unroll 8
    for (int tt = 0; tt < L_SEQ - P; tt++) {
        int j = tt & (P - 1);
        float u0 = u0b[j], u1 = u1b[j], u2 = u2b[j];
        float xv = __bfloat162float(xh[j]) + __bfloat162float(xl[j]);
        bool pad = (mkb[j] == 0);
        {   // prefetch tt+P
            const float* up = u + (size_t)(tt + P) * SU;
            u0b[j] = up[0]; u1b[j] = up[DIM]; u2b[j] = up[2 * DIM];
            xh[j] = hh[(size_t)(tt + P) * SH];
            xl[j] = hl[(size_t)(tt + P) * SH];
            mkb[j] = mk[tt + P];
        }
        float z = fmaf(vf, c, u1 + bf);
        float f = 1.f / (1.f + __expf(-z));
        float cn = fmaf(f, c - u0, u0);
        c = pad ? c : cn;
        if (!last) {
            float z2 = fmaf(vr, c, u2 + br);
            float r  = 1.f / (1.f + __expf(-z2));
            float ht = fmaf(r, c - xv, xv);
            ht = pad ? 0.f : ht;
            __nv_bfloat16 hi = __float2bfloat16(ht);
            __nv_bfloat16 lo = __float2bfloat16(ht - __bfloat162float(hi));
            hh[(size_t)tt * SH] = hi;
            hl[(size_t)tt * SH] = lo;
        }
    }
    #pragma unroll
    for (int tt = L_SEQ - P; tt < L_SEQ; tt++) {
        int j = tt & (P - 1);
        float u0 = u0b[j], u1 = u1b[j], u2 = u2b[j];
        float xv = __bfloat162float(xh[j]) + __bfloat162float(xl[j]);
        bool pad = (mkb[j] == 0);
        float z = fmaf(vf, c, u1 + bf);
        float f = 1.f / (1.f + __expf(-z));
        float cn = fmaf(f, c - u0, u0);
        c = pad ? c : cn;
        if (!last) {
            float z2 = fmaf(vr, c, u2 + br);
            float r  = 1.f / (1.f + __expf(-z2));
            float ht = fmaf(r, c - xv, xv);
            ht = pad ? 0.f : ht;
            __nv_bfloat16 hi = __float2bfloat16(ht);
            __nv_bfloat16 lo = __float2bfloat16(ht - __bfloat162float(hi));
            hh[(size_t)tt * SH] = hi;
            hl[(size_t)tt * SH] = lo;
        }
    }
    if (layer == 0) out[g] = c;
    else            out[g] += c;
}

// ---------------- launch -----------------------------------------------------
extern "C" void kernel_launch(void* const* d_in, const int* in_sizes, int n_in,
                              void* d_out, int out_size)
{
    const float* x     = (const float*)d_in[0];
    const int*   mask  = (const int*)  d_in[1];
    const float* state = (const float*)d_in[2];
    const float* W     = (const float*)d_in[3];
    const float* vc    = (const float*)d_in[4];
    const float* bias  = (const float*)d_in[5];
    float* out = (float*)d_out;

    cudaFuncSetAttribute(gemm_kernel,
                         cudaFuncAttributeMaxDynamicSharedMemorySize, SMEM_TOTAL);

    split_x_kernel<<<BATCH * L_SEQ, 128>>>(x);
    split_w_kernel<<<(NLAY * NTOT * DIM) / 256, 256>>>(W);

    for (int l = 0; l < NLAY; l++) {
        int nt = (l == NLAY - 1) ? 8 : 12;   // last layer: skip u2 tiles
        gemm_kernel<<<(MTOT / MT) * nt, 256, SMEM_TOTAL>>>(l, nt);
        recur_kernel<<<(BATCH * DIM) / 128, 128>>>(state, vc, bias, mask, out,
                                                   l, l == NLAY - 1);
    }
    (void)in_sizes; (void)n_in; (void)out_size;
}